// round 9
// baseline (speedup 1.0000x reference)
#include <cuda_runtime.h>
#include <cuda_bf16.h>
#include <cstdint>

// B=2, C=512, N=4096. out = x + Wo@Attn(GN(x)) + bo, [B,C,H,W] fp32.
#define BATCH 2
#define CCH   512
#define NPIX  4096
#define NQKV  1536
#define GEPS  1e-6f

static const long long CN   = (long long)CCH * NPIX;    // 2M
static const long long NN   = (long long)NPIX * NPIX;   // 16M
static const long long QKVN = (long long)NPIX * NQKV;   // 6M

// scratch (device globals)
__device__ __nv_bfloat16 g_ht [BATCH * NPIX * CCH];             // hT [B][pix][C]
__device__ __nv_bfloat16 g_qkv[(long long)BATCH * NPIX * NQKV]; // [B][pix][q|k|v]
__device__ __nv_bfloat16 g_p  [(long long)BATCH * NPIX * NPIX]; // exp(S) bf16
__device__ __nv_bfloat16 g_ot [BATCH * NPIX * CCH];             // OT [B][pix][C]
__device__ __nv_bfloat16 g_wqkv[NQKV * CCH];                    // concat(wq*s,wk,wv)
__device__ __nv_bfloat16 g_wo [CCH * CCH];
__device__ float         g_bqkv[NQKV];
__device__ float         g_rowsum[BATCH * NPIX];                // softmax denominators
__device__ float         g_stat[BATCH * 32 * 2];

// ---------------------------------------------------------------------------
// PTX helpers
// ---------------------------------------------------------------------------
__device__ __forceinline__ void cpasync16(uint32_t s, const void* g) {
    asm volatile("cp.async.cg.shared.global [%0], [%1], 16;" :: "r"(s), "l"(g));
}
__device__ __forceinline__ uint32_t smem_u32(const void* p) {
    return (uint32_t)__cvta_generic_to_shared(p);
}
__device__ __forceinline__ void ldsm4(uint32_t r[4], uint32_t addr) {
    asm volatile("ldmatrix.sync.aligned.m8n8.x4.shared.b16 {%0,%1,%2,%3}, [%4];"
        : "=r"(r[0]), "=r"(r[1]), "=r"(r[2]), "=r"(r[3]) : "r"(addr));
}
__device__ __forceinline__ void ldsm4t(uint32_t r[4], uint32_t addr) {
    asm volatile("ldmatrix.sync.aligned.m8n8.x4.trans.shared.b16 {%0,%1,%2,%3}, [%4];"
        : "=r"(r[0]), "=r"(r[1]), "=r"(r[2]), "=r"(r[3]) : "r"(addr));
}
__device__ __forceinline__ void mma_bf16(float c[4], const uint32_t a[4],
                                         const uint32_t b0, const uint32_t b1) {
    asm volatile(
        "mma.sync.aligned.m16n8k16.row.col.f32.bf16.bf16.f32 "
        "{%0,%1,%2,%3},{%4,%5,%6,%7},{%8,%9},{%0,%1,%2,%3};"
        : "+f"(c[0]), "+f"(c[1]), "+f"(c[2]), "+f"(c[3])
        : "r"(a[0]), "r"(a[1]), "r"(a[2]), "r"(a[3]), "r"(b0), "r"(b1));
}

// ---------------------------------------------------------------------------
// bf16 tensor-core GEMM: D[M][N] = A[M][K] * B^T
//   A bf16 [M][K]; TRB=0: B bf16 [N][K]; TRB=1: B bf16 [K][N] (ldmatrix.trans)
// Block tile 256x128x64, 256 thr = 8 warps (4m x 2n), WARP TILE 64x64,
// m16n8k16, 3-stage cp.async, 1 CTA/SM (regs ~230, smem 162KB).
// EPI: 1 = bf16 out + bias[n]
//      2 = expf + bf16 out + rowsum atomics (aux=rowsum, stride sAux)
//      3 = bf16 out * (1/rowsum[m])
//      4 = fp32 out + bias[m] + residual
// ---------------------------------------------------------------------------
#define BM 256
#define BN 128
#define BK 64
#define ASTR 144
#define BSTR_N 144
#define BSTR_T 272
#define ASTAGE (BM * ASTR)        // 36864
#define BSTAGE_N (BN * BSTR_N)    // 18432
#define BSTAGE_T (BK * BSTR_T)    // 17408
#define SMEM3_NT (3 * (ASTAGE + BSTAGE_N))   // 165888
#define SMEM3_TR (3 * (ASTAGE + BSTAGE_T))   // 162816

template<int EPI, bool TRB>
__global__ __launch_bounds__(256, 1) void gemm_bf16_tc(
    const __nv_bfloat16* __restrict__ A, const __nv_bfloat16* __restrict__ B,
    void* __restrict__ Cv,
    const float* __restrict__ aux, const float* __restrict__ res,
    int K, int lda, int ldb, int ldc,
    long long sA, long long sB, long long sC, long long sAux, long long sR)
{
    extern __shared__ char smem[];
    constexpr int BSTAGE = TRB ? BSTAGE_T : BSTAGE_N;
    const uint32_t sbA = smem_u32(smem);
    const uint32_t sbB = sbA + 3 * ASTAGE;

    const int tid  = threadIdx.x;
    const int wid  = tid >> 5;
    const int lane = tid & 31;
    const int g    = lane >> 2;
    const int tig  = lane & 3;
    const int sub  = lane >> 3;
    const int r8   = lane & 7;
    const int m_w  = (wid >> 1) * 64;     // 4 m-groups
    const int n_w  = (wid & 1) * 64;      // 2 n-groups
    const int m0   = blockIdx.y * BM;
    const int n0   = blockIdx.x * BN;
    const int z    = blockIdx.z;

    const __nv_bfloat16* Ab = A + (long long)z * sA + (long long)m0 * lda;
    const __nv_bfloat16* Bb = TRB ? (B + (long long)z * sB + n0)
                                  : (B + (long long)z * sB + (long long)n0 * ldb);

    float acc[4][8][4];
    #pragma unroll
    for (int i = 0; i < 4; i++)
        #pragma unroll
        for (int j = 0; j < 8; j++)
            #pragma unroll
            for (int r = 0; r < 4; r++) acc[i][j][r] = 0.f;

    const int nk = K / BK;

    auto load = [&](int ks, int buf) {
        const uint32_t ab = sbA + buf * ASTAGE;
        const uint32_t bb = sbB + buf * BSTAGE;
        #pragma unroll
        for (int it = 0; it < 8; it++) {           // A: 2048 x 16B chunks
            int s = tid + it * 256;
            int r = s >> 3, c = s & 7;
            cpasync16(ab + r * ASTR + c * 16,
                      Ab + (long long)r * lda + ks * BK + c * 8);
        }
        if (!TRB) {
            #pragma unroll
            for (int it = 0; it < 4; it++) {       // B: 128 n-rows x 8 chunks
                int s = tid + it * 256;
                int r = s >> 3, c = s & 7;
                cpasync16(bb + r * BSTR_N + c * 16,
                          Bb + (long long)r * ldb + ks * BK + c * 8);
            }
        } else {
            #pragma unroll
            for (int it = 0; it < 4; it++) {       // B: 64 k-rows x 16 chunks
                int s = tid + it * 256;
                int r = s >> 4, c = s & 15;
                cpasync16(bb + r * BSTR_T + c * 16,
                          Bb + (long long)(ks * BK + r) * ldb + c * 8);
            }
        }
        asm volatile("cp.async.commit_group;");
    };

    load(0, 0);
    if (nk > 1) load(1, 1);

    #pragma unroll 1
    for (int ks = 0; ks < nk; ks++) {
        const int buf = ks % 3;
        if (ks + 1 < nk) asm volatile("cp.async.wait_group 1;");
        else             asm volatile("cp.async.wait_group 0;");
        __syncthreads();
        if (ks + 2 < nk) load(ks + 2, (ks + 2) % 3);

        const uint32_t ab = sbA + buf * ASTAGE;
        const uint32_t bb = sbB + buf * BSTAGE;

        #pragma unroll
        for (int kk = 0; kk < 4; kk++) {
            uint32_t af[4][4];
            #pragma unroll
            for (int i = 0; i < 4; i++) {
                uint32_t addr = ab + (m_w + 16 * i + (sub & 1) * 8 + r8) * ASTR
                              + kk * 32 + (sub >> 1) * 16;
                ldsm4(af[i], addr);
            }
            uint32_t bf[8][2];
            #pragma unroll
            for (int jj = 0; jj < 4; jj++) {
                uint32_t t[4];
                if (!TRB) {
                    uint32_t addr = bb + (n_w + 16 * jj + (sub >> 1) * 8 + r8) * BSTR_N
                                  + kk * 32 + (sub & 1) * 16;
                    ldsm4(t, addr);
                } else {
                    uint32_t addr = bb + (kk * 16 + (sub & 1) * 8 + r8) * BSTR_T
                                  + (n_w + 16 * jj + (sub >> 1) * 8) * 2;
                    ldsm4t(t, addr);
                }
                bf[2 * jj][0] = t[0]; bf[2 * jj][1] = t[1];
                bf[2 * jj + 1][0] = t[2]; bf[2 * jj + 1][1] = t[3];
            }
            #pragma unroll
            for (int i = 0; i < 4; i++)
                #pragma unroll
                for (int j = 0; j < 8; j++)
                    mma_bf16(acc[i][j], af[i], bf[j][0], bf[j][1]);
        }
    }

    // ------------------------------ epilogues ------------------------------
    if (EPI == 1) {           // bf16 out + bias[n]
        __nv_bfloat16* C = (__nv_bfloat16*)Cv + (long long)z * sC;
        #pragma unroll
        for (int i = 0; i < 4; i++) {
            int r0 = m0 + m_w + 16 * i + g, r1 = r0 + 8;
            #pragma unroll
            for (int j = 0; j < 8; j++) {
                int col = n0 + n_w + 8 * j + 2 * tig;
                float bn0 = aux[col], bn1 = aux[col + 1];
                *(__nv_bfloat162*)&C[(long long)r0 * ldc + col] =
                    __float22bfloat162_rn(make_float2(acc[i][j][0] + bn0,
                                                      acc[i][j][1] + bn1));
                *(__nv_bfloat162*)&C[(long long)r1 * ldc + col] =
                    __float22bfloat162_rn(make_float2(acc[i][j][2] + bn0,
                                                      acc[i][j][3] + bn1));
            }
        }
    } else if (EPI == 2) {    // expf, bf16 out, rowsum atomics
        __nv_bfloat16* C = (__nv_bfloat16*)Cv + (long long)z * sC;
        float* rs = (float*)aux + (long long)z * sAux;
        #pragma unroll
        for (int i = 0; i < 4; i++) {
            int r0 = m0 + m_w + 16 * i + g, r1 = r0 + 8;
            float s0 = 0.f, s1 = 0.f;
            #pragma unroll
            for (int j = 0; j < 8; j++) {
                int col = n0 + n_w + 8 * j + 2 * tig;
                float e0 = __expf(acc[i][j][0]);
                float e1 = __expf(acc[i][j][1]);
                float e2 = __expf(acc[i][j][2]);
                float e3 = __expf(acc[i][j][3]);
                s0 += e0 + e1; s1 += e2 + e3;
                *(__nv_bfloat162*)&C[(long long)r0 * ldc + col] =
                    __float22bfloat162_rn(make_float2(e0, e1));
                *(__nv_bfloat162*)&C[(long long)r1 * ldc + col] =
                    __float22bfloat162_rn(make_float2(e2, e3));
            }
            s0 += __shfl_xor_sync(0xffffffffu, s0, 1);
            s0 += __shfl_xor_sync(0xffffffffu, s0, 2);
            s1 += __shfl_xor_sync(0xffffffffu, s1, 1);
            s1 += __shfl_xor_sync(0xffffffffu, s1, 2);
            if (tig == 0) {
                atomicAdd(&rs[r0], s0);
                atomicAdd(&rs[r1], s1);
            }
        }
    } else if (EPI == 3) {    // bf16 out scaled by 1/rowsum[m]
        __nv_bfloat16* C = (__nv_bfloat16*)Cv + (long long)z * sC;
        const float* rs = aux + (long long)z * sAux;
        #pragma unroll
        for (int i = 0; i < 4; i++) {
            int r0 = m0 + m_w + 16 * i + g, r1 = r0 + 8;
            float i0 = 1.f / rs[r0];
            float i1 = 1.f / rs[r1];
            #pragma unroll
            for (int j = 0; j < 8; j++) {
                int col = n0 + n_w + 8 * j + 2 * tig;
                *(__nv_bfloat162*)&C[(long long)r0 * ldc + col] =
                    __float22bfloat162_rn(make_float2(acc[i][j][0] * i0,
                                                      acc[i][j][1] * i0));
                *(__nv_bfloat162*)&C[(long long)r1 * ldc + col] =
                    __float22bfloat162_rn(make_float2(acc[i][j][2] * i1,
                                                      acc[i][j][3] * i1));
            }
        }
    } else {                  // EPI == 4: fp32 out + bias[m] + residual
        float* C = (float*)Cv + (long long)z * sC;
        const float* Rb = res + (long long)z * sR;
        #pragma unroll
        for (int i = 0; i < 4; i++) {
            int r0 = m0 + m_w + 16 * i + g, r1 = r0 + 8;
            float bm0 = aux[r0], bm1 = aux[r1];
            #pragma unroll
            for (int j = 0; j < 8; j++) {
                int col = n0 + n_w + 8 * j + 2 * tig;
                long long o0 = (long long)r0 * ldc + col;
                long long o1 = (long long)r1 * ldc + col;
                float2 a0 = *(const float2*)&Rb[o0];
                float2 a1 = *(const float2*)&Rb[o1];
                float2 v0 = make_float2(acc[i][j][0] + bm0 + a0.x,
                                        acc[i][j][1] + bm0 + a0.y);
                float2 v1 = make_float2(acc[i][j][2] + bm1 + a1.x,
                                        acc[i][j][3] + bm1 + a1.y);
                *(float2*)&C[o0] = v0;
                *(float2*)&C[o1] = v1;
            }
        }
    }
}

// ---------------------------------------------------------------------------
__global__ __launch_bounds__(256) void zero_rowsum(float* __restrict__ rs)
{
    rs[blockIdx.x * 256 + threadIdx.x] = 0.f;
}

__global__ __launch_bounds__(256) void prep_weights(
    const float* __restrict__ wq, const float* __restrict__ wk,
    const float* __restrict__ wv, const float* __restrict__ wo,
    const float* __restrict__ bq, const float* __restrict__ bk,
    const float* __restrict__ bv,
    __nv_bfloat16* __restrict__ wqkv, __nv_bfloat16* __restrict__ wob,
    float* __restrict__ bqkv)
{
    const float scale = 0.044194173824159216f;   // 512^-0.5
    int idx = blockIdx.x * 256 + threadIdx.x;
    if (idx < NQKV * CCH) {
        int row = idx >> 9, col = idx & 511;
        int which = row >> 9, rr = row & 511;
        float v = which == 0 ? wq[rr * 512 + col] * scale
                : which == 1 ? wk[rr * 512 + col]
                             : wv[rr * 512 + col];
        wqkv[idx] = __float2bfloat16_rn(v);
        if (idx < NQKV) {
            int w2 = idx >> 9, r2 = idx & 511;
            bqkv[idx] = w2 == 0 ? bq[r2] * scale : w2 == 1 ? bk[r2] : bv[r2];
        }
    } else {
        int j = idx - NQKV * CCH;
        wob[j] = __float2bfloat16_rn(wo[j]);
    }
}

__global__ __launch_bounds__(256) void gn_stats_kernel(
    const float* __restrict__ x, float* __restrict__ stat)
{
    const int bg = blockIdx.x;
    const long long base = (long long)bg * 65536;
    const int t = threadIdx.x;
    float s = 0.f, ss = 0.f;
    #pragma unroll 8
    for (int i = t; i < 65536; i += 256) {
        float v = x[base + i];
        s += v; ss += v * v;
    }
    #pragma unroll
    for (int off = 16; off; off >>= 1) {
        s  += __shfl_down_sync(0xffffffffu, s,  off);
        ss += __shfl_down_sync(0xffffffffu, ss, off);
    }
    __shared__ float shs[8], shss[8];
    int wid = t >> 5, lane = t & 31;
    if (lane == 0) { shs[wid] = s; shss[wid] = ss; }
    __syncthreads();
    if (t == 0) {
        float ts = 0.f, tss = 0.f;
        #pragma unroll
        for (int i = 0; i < 8; i++) { ts += shs[i]; tss += shss[i]; }
        float mean = ts * (1.f / 65536.f);
        float var  = tss * (1.f / 65536.f) - mean * mean;
        stat[2 * bg]     = mean;
        stat[2 * bg + 1] = rsqrtf(var + GEPS);
    }
}

__global__ __launch_bounds__(256) void gn_apply_t_kernel(
    const float* __restrict__ x, const float* __restrict__ w,
    const float* __restrict__ b, const float* __restrict__ stat,
    __nv_bfloat16* __restrict__ ht)
{
    __shared__ float tile[32][33];
    const int p0 = blockIdx.x * 32;
    const int c0 = blockIdx.y * 32;
    const int bb = blockIdx.z;
    const int tx = threadIdx.x, ty = threadIdx.y;   // (32, 8)
    const long long xb = (long long)bb * CN;

    #pragma unroll
    for (int r = 0; r < 4; r++) {
        int cl = ty + 8 * r;
        tile[cl][tx] = x[xb + (long long)(c0 + cl) * NPIX + p0 + tx];
    }
    __syncthreads();
    const int c = c0 + tx;
    const int gidx = c >> 4;
    const float mean = stat[2 * (bb * 32 + gidx)];
    const float rstd = stat[2 * (bb * 32 + gidx) + 1];
    const float sc = rstd * w[c];
    const float sh = b[c] - mean * sc;
    #pragma unroll
    for (int r = 0; r < 4; r++) {
        int pl = ty + 8 * r;
        float v = tile[tx][pl] * sc + sh;
        ht[xb + (long long)(p0 + pl) * CCH + c] = __float2bfloat16_rn(v);
    }
}

// ---------------------------------------------------------------------------
extern "C" void kernel_launch(void* const* d_in, const int* in_sizes, int n_in,
                              void* d_out, int out_size)
{
    const float* x    = (const float*)d_in[0];
    const float* gn_w = (const float*)d_in[1];
    const float* gn_b = (const float*)d_in[2];
    const float* wq   = (const float*)d_in[3];
    const float* bq   = (const float*)d_in[4];
    const float* wk   = (const float*)d_in[5];
    const float* bk   = (const float*)d_in[6];
    const float* wv   = (const float*)d_in[7];
    const float* bv   = (const float*)d_in[8];
    const float* wo   = (const float*)d_in[9];
    const float* bo   = (const float*)d_in[10];
    float* out = (float*)d_out;

    __nv_bfloat16 *ht, *qkv, *p, *ot, *wqkv, *wob;
    float *bqkv, *stat, *rowsum;
    cudaGetSymbolAddress((void**)&ht,     g_ht);
    cudaGetSymbolAddress((void**)&qkv,    g_qkv);
    cudaGetSymbolAddress((void**)&p,      g_p);
    cudaGetSymbolAddress((void**)&ot,     g_ot);
    cudaGetSymbolAddress((void**)&wqkv,   g_wqkv);
    cudaGetSymbolAddress((void**)&wob,    g_wo);
    cudaGetSymbolAddress((void**)&bqkv,   g_bqkv);
    cudaGetSymbolAddress((void**)&stat,   g_stat);
    cudaGetSymbolAddress((void**)&rowsum, g_rowsum);

    cudaFuncSetAttribute(gemm_bf16_tc<1, false>,
        cudaFuncAttributeMaxDynamicSharedMemorySize, SMEM3_NT);
    cudaFuncSetAttribute(gemm_bf16_tc<2, false>,
        cudaFuncAttributeMaxDynamicSharedMemorySize, SMEM3_NT);
    cudaFuncSetAttribute(gemm_bf16_tc<3, true>,
        cudaFuncAttributeMaxDynamicSharedMemorySize, SMEM3_TR);
    cudaFuncSetAttribute(gemm_bf16_tc<4, false>,
        cudaFuncAttributeMaxDynamicSharedMemorySize, SMEM3_NT);

    // 0) zero softmax denominators; prep weights
    zero_rowsum<<<BATCH * NPIX / 256, 256>>>(rowsum);
    prep_weights<<<(NQKV * CCH + CCH * CCH) / 256, 256>>>(
        wq, wk, wv, wo, bq, bk, bv, wqkv, wob, bqkv);

    // 1) GroupNorm -> hT bf16 [B][pix][C]
    gn_stats_kernel<<<BATCH * 32, 256>>>(x, stat);
    gn_apply_t_kernel<<<dim3(NPIX / 32, CCH / 32, BATCH), dim3(32, 8)>>>(
        x, gn_w, gn_b, stat, ht);

    // 2) fused QKV: qkvT[pix][1536] = hT @ wqkv^T + bqkv[n]
    dim3 gQKV(NQKV / BN, NPIX / BM, BATCH);       // (12, 16, 2)
    gemm_bf16_tc<1, false><<<gQKV, 256, SMEM3_NT>>>(
        ht, wqkv, qkv, bqkv, nullptr, CCH, CCH, CCH, NQKV,
        CN, 0, QKVN, 0, 0);

    // 3) P = exp(qT @ kT^T) -> bf16, rowsum accumulated
    dim3 gS(NPIX / BN, NPIX / BM, BATCH);         // (32, 16, 2)
    gemm_bf16_tc<2, false><<<gS, 256, SMEM3_NT>>>(
        qkv, qkv + 512, p, rowsum, nullptr, CCH, NQKV, NQKV, NPIX,
        QKVN, QKVN, NN, NPIX, 0);

    // 4) OT[pix][C] = (P @ vT) / rowsum[pix]
    dim3 gAV(CCH / BN, NPIX / BM, BATCH);         // (4, 16, 2)
    gemm_bf16_tc<3, true><<<gAV, 256, SMEM3_TR>>>(
        p, qkv + 1024, ot, rowsum, nullptr, NPIX, NPIX, NQKV, CCH,
        NN, QKVN, CN, NPIX, 0);

    // 5) out = x + wo @ OT^T + bo[m]  (fp32)
    dim3 gF(NPIX / BN, CCH / BM, BATCH);          // (32, 2, 2)
    gemm_bf16_tc<4, false><<<gF, 256, SMEM3_NT>>>(
        wob, ot, out, bo, x, CCH, CCH, CCH, NPIX,
        0, CN, CN, 0, CN);
}

// round 10
// speedup vs baseline: 1.0565x; 1.0565x over previous
#include <cuda_runtime.h>
#include <cuda_bf16.h>
#include <cstdint>

// B=2, C=512, N=4096. out = x + Wo@Attn(GN(x)) + bo, [B,C,H,W] fp32.
#define BATCH 2
#define CCH   512
#define NPIX  4096
#define NQKV  1536
#define GEPS  1e-6f

static const long long CN   = (long long)CCH * NPIX;    // 2M
static const long long NN   = (long long)NPIX * NPIX;   // 16M
static const long long QKVN = (long long)NPIX * NQKV;   // 6M

// scratch (device globals)
__device__ __nv_bfloat16 g_ht [BATCH * NPIX * CCH];             // hT [B][pix][C]
__device__ __nv_bfloat16 g_qkv[(long long)BATCH * NPIX * NQKV]; // [B][pix][q|k|v]
__device__ __nv_bfloat16 g_p  [(long long)BATCH * NPIX * NPIX]; // exp(S) bf16
__device__ __nv_bfloat16 g_ot [BATCH * NPIX * CCH];             // OT [B][pix][C]
__device__ __nv_bfloat16 g_wqkv[NQKV * CCH];                    // concat(wq*s,wk,wv)
__device__ __nv_bfloat16 g_wo [CCH * CCH];
__device__ float         g_bqkv[NQKV];
__device__ float         g_rowsum[BATCH * NPIX];                // softmax denominators
__device__ float         g_ssum[BATCH * 32 * 2];                // GN (sum, sumsq)

// ---------------------------------------------------------------------------
// PTX helpers
// ---------------------------------------------------------------------------
__device__ __forceinline__ void cpasync16(uint32_t s, const void* g) {
    asm volatile("cp.async.cg.shared.global [%0], [%1], 16;" :: "r"(s), "l"(g));
}
__device__ __forceinline__ uint32_t smem_u32(const void* p) {
    return (uint32_t)__cvta_generic_to_shared(p);
}
__device__ __forceinline__ void ldsm4(uint32_t r[4], uint32_t addr) {
    asm volatile("ldmatrix.sync.aligned.m8n8.x4.shared.b16 {%0,%1,%2,%3}, [%4];"
        : "=r"(r[0]), "=r"(r[1]), "=r"(r[2]), "=r"(r[3]) : "r"(addr));
}
__device__ __forceinline__ void ldsm4t(uint32_t r[4], uint32_t addr) {
    asm volatile("ldmatrix.sync.aligned.m8n8.x4.trans.shared.b16 {%0,%1,%2,%3}, [%4];"
        : "=r"(r[0]), "=r"(r[1]), "=r"(r[2]), "=r"(r[3]) : "r"(addr));
}
__device__ __forceinline__ void mma_bf16(float c[4], const uint32_t a[4],
                                         const uint32_t b0, const uint32_t b1) {
    asm volatile(
        "mma.sync.aligned.m16n8k16.row.col.f32.bf16.bf16.f32 "
        "{%0,%1,%2,%3},{%4,%5,%6,%7},{%8,%9},{%0,%1,%2,%3};"
        : "+f"(c[0]), "+f"(c[1]), "+f"(c[2]), "+f"(c[3])
        : "r"(a[0]), "r"(a[1]), "r"(a[2]), "r"(a[3]), "r"(b0), "r"(b1));
}

// ---------------------------------------------------------------------------
// bf16 tensor-core GEMM (R8-best config): D[M][N] = A[M][K] * B^T
//   A bf16 [M][K]; TRB=0: B bf16 [N][K]; TRB=1: B bf16 [K][N] (ldmatrix.trans)
// Block 128x128x64, 256 thr = 8 warps (2x4), warp tile 64x32, m16n8k16,
// 3-stage cp.async, 2 CTAs/SM.
// EPI: 1 = bf16 out + bias[n]
//      2 = expf + bf16 out + rowsum atomics (aux=rowsum, stride sAux)
//      3 = bf16 out * (1/rowsum[m])
//      4 = fp32 out + bias[m] + residual
// ---------------------------------------------------------------------------
#define BM 128
#define BN 128
#define BK 64
#define ASTR 144
#define BSTR_N 144
#define BSTR_T 272
#define ASTAGE (BM * ASTR)
#define BSTAGE_N (BN * BSTR_N)
#define BSTAGE_T (BK * BSTR_T)
#define SMEM3_NT (3 * (ASTAGE + BSTAGE_N))   // 110592
#define SMEM3_TR (3 * (ASTAGE + BSTAGE_T))   // 107520

template<int EPI, bool TRB>
__global__ __launch_bounds__(256, 2) void gemm_bf16_tc(
    const __nv_bfloat16* __restrict__ A, const __nv_bfloat16* __restrict__ B,
    void* __restrict__ Cv,
    const float* __restrict__ aux, const float* __restrict__ res,
    int K, int lda, int ldb, int ldc,
    long long sA, long long sB, long long sC, long long sAux, long long sR)
{
    extern __shared__ char smem[];
    constexpr int BSTAGE = TRB ? BSTAGE_T : BSTAGE_N;
    const uint32_t sbA = smem_u32(smem);
    const uint32_t sbB = sbA + 3 * ASTAGE;

    const int tid  = threadIdx.x;
    const int wid  = tid >> 5;
    const int lane = tid & 31;
    const int g    = lane >> 2;
    const int tig  = lane & 3;
    const int sub  = lane >> 3;
    const int r8   = lane & 7;
    const int m_w  = (wid >> 2) * 64;
    const int n_w  = (wid & 3) * 32;
    const int m0   = blockIdx.y * BM;
    const int n0   = blockIdx.x * BN;
    const int z    = blockIdx.z;

    const __nv_bfloat16* Ab = A + (long long)z * sA + (long long)m0 * lda;
    const __nv_bfloat16* Bb = TRB ? (B + (long long)z * sB + n0)
                                  : (B + (long long)z * sB + (long long)n0 * ldb);

    float acc[4][4][4];
    #pragma unroll
    for (int i = 0; i < 4; i++)
        #pragma unroll
        for (int j = 0; j < 4; j++)
            #pragma unroll
            for (int r = 0; r < 4; r++) acc[i][j][r] = 0.f;

    const int nk = K / BK;

    auto load = [&](int ks, int buf) {
        const uint32_t ab = sbA + buf * ASTAGE;
        const uint32_t bb = sbB + buf * BSTAGE;
        #pragma unroll
        for (int it = 0; it < 4; it++) {
            int s = tid + it * 256;
            int r = s >> 3, c = s & 7;
            cpasync16(ab + r * ASTR + c * 16,
                      Ab + (long long)r * lda + ks * BK + c * 8);
        }
        if (!TRB) {
            #pragma unroll
            for (int it = 0; it < 4; it++) {
                int s = tid + it * 256;
                int r = s >> 3, c = s & 7;
                cpasync16(bb + r * BSTR_N + c * 16,
                          Bb + (long long)r * ldb + ks * BK + c * 8);
            }
        } else {
            #pragma unroll
            for (int it = 0; it < 4; it++) {
                int s = tid + it * 256;
                int r = s >> 4, c = s & 15;
                cpasync16(bb + r * BSTR_T + c * 16,
                          Bb + (long long)(ks * BK + r) * ldb + c * 8);
            }
        }
        asm volatile("cp.async.commit_group;");
    };

    load(0, 0);
    if (nk > 1) load(1, 1);

    #pragma unroll 1
    for (int ks = 0; ks < nk; ks++) {
        const int buf = ks % 3;
        if (ks + 1 < nk) asm volatile("cp.async.wait_group 1;");
        else             asm volatile("cp.async.wait_group 0;");
        __syncthreads();
        if (ks + 2 < nk) load(ks + 2, (ks + 2) % 3);

        const uint32_t ab = sbA + buf * ASTAGE;
        const uint32_t bb = sbB + buf * BSTAGE;

        #pragma unroll
        for (int kk = 0; kk < 4; kk++) {
            uint32_t af[4][4];
            #pragma unroll
            for (int i = 0; i < 4; i++) {
                uint32_t addr = ab + (m_w + 16 * i + (sub & 1) * 8 + r8) * ASTR
                              + kk * 32 + (sub >> 1) * 16;
                ldsm4(af[i], addr);
            }
            uint32_t bf[4][2];
            #pragma unroll
            for (int jj = 0; jj < 2; jj++) {
                uint32_t t[4];
                if (!TRB) {
                    uint32_t addr = bb + (n_w + 16 * jj + (sub >> 1) * 8 + r8) * BSTR_N
                                  + kk * 32 + (sub & 1) * 16;
                    ldsm4(t, addr);
                } else {
                    uint32_t addr = bb + (kk * 16 + (sub & 1) * 8 + r8) * BSTR_T
                                  + (n_w + 16 * jj + (sub >> 1) * 8) * 2;
                    ldsm4t(t, addr);
                }
                bf[2 * jj][0] = t[0]; bf[2 * jj][1] = t[1];
                bf[2 * jj + 1][0] = t[2]; bf[2 * jj + 1][1] = t[3];
            }
            #pragma unroll
            for (int i = 0; i < 4; i++)
                #pragma unroll
                for (int j = 0; j < 4; j++)
                    mma_bf16(acc[i][j], af[i], bf[j][0], bf[j][1]);
        }
    }

    // ------------------------------ epilogues ------------------------------
    if (EPI == 1) {           // bf16 out + bias[n]
        __nv_bfloat16* C = (__nv_bfloat16*)Cv + (long long)z * sC;
        #pragma unroll
        for (int i = 0; i < 4; i++) {
            int r0 = m0 + m_w + 16 * i + g, r1 = r0 + 8;
            #pragma unroll
            for (int j = 0; j < 4; j++) {
                int col = n0 + n_w + 8 * j + 2 * tig;
                float bn0 = aux[col], bn1 = aux[col + 1];
                *(__nv_bfloat162*)&C[(long long)r0 * ldc + col] =
                    __float22bfloat162_rn(make_float2(acc[i][j][0] + bn0,
                                                      acc[i][j][1] + bn1));
                *(__nv_bfloat162*)&C[(long long)r1 * ldc + col] =
                    __float22bfloat162_rn(make_float2(acc[i][j][2] + bn0,
                                                      acc[i][j][3] + bn1));
            }
        }
    } else if (EPI == 2) {    // expf, bf16 out, rowsum atomics
        __nv_bfloat16* C = (__nv_bfloat16*)Cv + (long long)z * sC;
        float* rs = (float*)aux + (long long)z * sAux;
        #pragma unroll
        for (int i = 0; i < 4; i++) {
            int r0 = m0 + m_w + 16 * i + g, r1 = r0 + 8;
            float s0 = 0.f, s1 = 0.f;
            #pragma unroll
            for (int j = 0; j < 4; j++) {
                int col = n0 + n_w + 8 * j + 2 * tig;
                float e0 = __expf(acc[i][j][0]);
                float e1 = __expf(acc[i][j][1]);
                float e2 = __expf(acc[i][j][2]);
                float e3 = __expf(acc[i][j][3]);
                s0 += e0 + e1; s1 += e2 + e3;
                *(__nv_bfloat162*)&C[(long long)r0 * ldc + col] =
                    __float22bfloat162_rn(make_float2(e0, e1));
                *(__nv_bfloat162*)&C[(long long)r1 * ldc + col] =
                    __float22bfloat162_rn(make_float2(e2, e3));
            }
            s0 += __shfl_xor_sync(0xffffffffu, s0, 1);
            s0 += __shfl_xor_sync(0xffffffffu, s0, 2);
            s1 += __shfl_xor_sync(0xffffffffu, s1, 1);
            s1 += __shfl_xor_sync(0xffffffffu, s1, 2);
            if (tig == 0) {
                atomicAdd(&rs[r0], s0);
                atomicAdd(&rs[r1], s1);
            }
        }
    } else if (EPI == 3) {    // bf16 out scaled by 1/rowsum[m]
        __nv_bfloat16* C = (__nv_bfloat16*)Cv + (long long)z * sC;
        const float* rs = aux + (long long)z * sAux;
        #pragma unroll
        for (int i = 0; i < 4; i++) {
            int r0 = m0 + m_w + 16 * i + g, r1 = r0 + 8;
            float i0 = 1.f / rs[r0];
            float i1 = 1.f / rs[r1];
            #pragma unroll
            for (int j = 0; j < 4; j++) {
                int col = n0 + n_w + 8 * j + 2 * tig;
                *(__nv_bfloat162*)&C[(long long)r0 * ldc + col] =
                    __float22bfloat162_rn(make_float2(acc[i][j][0] * i0,
                                                      acc[i][j][1] * i0));
                *(__nv_bfloat162*)&C[(long long)r1 * ldc + col] =
                    __float22bfloat162_rn(make_float2(acc[i][j][2] * i1,
                                                      acc[i][j][3] * i1));
            }
        }
    } else {                  // EPI == 4: fp32 out + bias[m] + residual
        float* C = (float*)Cv + (long long)z * sC;
        const float* Rb = res + (long long)z * sR;
        #pragma unroll
        for (int i = 0; i < 4; i++) {
            int r0 = m0 + m_w + 16 * i + g, r1 = r0 + 8;
            float bm0 = aux[r0], bm1 = aux[r1];
            #pragma unroll
            for (int j = 0; j < 4; j++) {
                int col = n0 + n_w + 8 * j + 2 * tig;
                long long o0 = (long long)r0 * ldc + col;
                long long o1 = (long long)r1 * ldc + col;
                float2 a0 = *(const float2*)&Rb[o0];
                float2 a1 = *(const float2*)&Rb[o1];
                float2 v0 = make_float2(acc[i][j][0] + bm0 + a0.x,
                                        acc[i][j][1] + bm0 + a0.y);
                float2 v1 = make_float2(acc[i][j][2] + bm1 + a1.x,
                                        acc[i][j][3] + bm1 + a1.y);
                *(float2*)&C[o0] = v0;
                *(float2*)&C[o1] = v1;
            }
        }
    }
}

// ---------------------------------------------------------------------------
// zero rowsum + GN stat accumulators in one launch
// ---------------------------------------------------------------------------
__global__ __launch_bounds__(256) void zero_aux(
    float* __restrict__ rs, float* __restrict__ ssum)
{
    int idx = blockIdx.x * 256 + threadIdx.x;
    if (idx < BATCH * NPIX) rs[idx] = 0.f;
    if (idx < BATCH * 32 * 2) ssum[idx] = 0.f;
}

// ---------------------------------------------------------------------------
// Weight/bias prep: concat(wq*s, wk, wv) -> bf16; wo -> bf16; bias concat.
// ---------------------------------------------------------------------------
__global__ __launch_bounds__(256) void prep_weights(
    const float* __restrict__ wq, const float* __restrict__ wk,
    const float* __restrict__ wv, const float* __restrict__ wo,
    const float* __restrict__ bq, const float* __restrict__ bk,
    const float* __restrict__ bv,
    __nv_bfloat16* __restrict__ wqkv, __nv_bfloat16* __restrict__ wob,
    float* __restrict__ bqkv)
{
    const float scale = 0.044194173824159216f;   // 512^-0.5
    int idx = blockIdx.x * 256 + threadIdx.x;
    if (idx < NQKV * CCH) {
        int row = idx >> 9, col = idx & 511;
        int which = row >> 9, rr = row & 511;
        float v = which == 0 ? wq[rr * 512 + col] * scale
                : which == 1 ? wk[rr * 512 + col]
                             : wv[rr * 512 + col];
        wqkv[idx] = __float2bfloat16_rn(v);
        if (idx < NQKV) {
            int w2 = idx >> 9, r2 = idx & 511;
            bqkv[idx] = w2 == 0 ? bq[r2] * scale : w2 == 1 ? bk[r2] : bv[r2];
        }
    } else {
        int j = idx - NQKV * CCH;
        wob[j] = __float2bfloat16_rn(wo[j]);
    }
}

// ---------------------------------------------------------------------------
// GN partial stats: 4 blocks per (b,group); atomicAdd (sum, sumsq)
// ---------------------------------------------------------------------------
__global__ __launch_bounds__(256) void gn_stats_part(
    const float* __restrict__ x, float* __restrict__ ssum)
{
    const int bg   = blockIdx.x >> 2;
    const int part = blockIdx.x & 3;
    const long long base = (long long)bg * 65536 + part * 16384;
    const int t = threadIdx.x;
    float s = 0.f, ss = 0.f;
    #pragma unroll 4
    for (int i = t; i < 16384; i += 256) {
        float v = x[base + i];
        s += v; ss += v * v;
    }
    #pragma unroll
    for (int off = 16; off; off >>= 1) {
        s  += __shfl_down_sync(0xffffffffu, s,  off);
        ss += __shfl_down_sync(0xffffffffu, ss, off);
    }
    __shared__ float shs[8], shss[8];
    int wid = t >> 5, lane = t & 31;
    if (lane == 0) { shs[wid] = s; shss[wid] = ss; }
    __syncthreads();
    if (t == 0) {
        float ts = 0.f, tss = 0.f;
        #pragma unroll
        for (int i = 0; i < 8; i++) { ts += shs[i]; tss += shss[i]; }
        atomicAdd(&ssum[2 * bg],     ts);
        atomicAdd(&ssum[2 * bg + 1], tss);
    }
}

// GN apply + transpose (bf16 out); computes mean/rstd from raw sums
__global__ __launch_bounds__(256) void gn_apply_t_kernel(
    const float* __restrict__ x, const float* __restrict__ w,
    const float* __restrict__ b, const float* __restrict__ ssum,
    __nv_bfloat16* __restrict__ ht)
{
    __shared__ float tile[32][33];
    const int p0 = blockIdx.x * 32;
    const int c0 = blockIdx.y * 32;
    const int bb = blockIdx.z;
    const int tx = threadIdx.x, ty = threadIdx.y;   // (32, 8)
    const long long xb = (long long)bb * CN;

    #pragma unroll
    for (int r = 0; r < 4; r++) {
        int cl = ty + 8 * r;
        tile[cl][tx] = x[xb + (long long)(c0 + cl) * NPIX + p0 + tx];
    }
    __syncthreads();
    const int c = c0 + tx;
    const int gidx = c >> 4;
    const float ts  = ssum[2 * (bb * 32 + gidx)];
    const float tss = ssum[2 * (bb * 32 + gidx) + 1];
    const float mean = ts * (1.f / 65536.f);
    const float var  = tss * (1.f / 65536.f) - mean * mean;
    const float rstd = rsqrtf(var + GEPS);
    const float sc = rstd * w[c];
    const float sh = b[c] - mean * sc;
    #pragma unroll
    for (int r = 0; r < 4; r++) {
        int pl = ty + 8 * r;
        float v = tile[tx][pl] * sc + sh;
        ht[xb + (long long)(p0 + pl) * CCH + c] = __float2bfloat16_rn(v);
    }
}

// ---------------------------------------------------------------------------
extern "C" void kernel_launch(void* const* d_in, const int* in_sizes, int n_in,
                              void* d_out, int out_size)
{
    const float* x    = (const float*)d_in[0];
    const float* gn_w = (const float*)d_in[1];
    const float* gn_b = (const float*)d_in[2];
    const float* wq   = (const float*)d_in[3];
    const float* bq   = (const float*)d_in[4];
    const float* wk   = (const float*)d_in[5];
    const float* bk   = (const float*)d_in[6];
    const float* wv   = (const float*)d_in[7];
    const float* bv   = (const float*)d_in[8];
    const float* wo   = (const float*)d_in[9];
    const float* bo   = (const float*)d_in[10];
    float* out = (float*)d_out;

    __nv_bfloat16 *ht, *qkv, *p, *ot, *wqkv, *wob;
    float *bqkv, *ssum, *rowsum;
    cudaGetSymbolAddress((void**)&ht,     g_ht);
    cudaGetSymbolAddress((void**)&qkv,    g_qkv);
    cudaGetSymbolAddress((void**)&p,      g_p);
    cudaGetSymbolAddress((void**)&ot,     g_ot);
    cudaGetSymbolAddress((void**)&wqkv,   g_wqkv);
    cudaGetSymbolAddress((void**)&wob,    g_wo);
    cudaGetSymbolAddress((void**)&bqkv,   g_bqkv);
    cudaGetSymbolAddress((void**)&ssum,   g_ssum);
    cudaGetSymbolAddress((void**)&rowsum, g_rowsum);

    cudaFuncSetAttribute(gemm_bf16_tc<1, false>,
        cudaFuncAttributeMaxDynamicSharedMemorySize, SMEM3_NT);
    cudaFuncSetAttribute(gemm_bf16_tc<2, false>,
        cudaFuncAttributeMaxDynamicSharedMemorySize, SMEM3_NT);
    cudaFuncSetAttribute(gemm_bf16_tc<3, true>,
        cudaFuncAttributeMaxDynamicSharedMemorySize, SMEM3_TR);
    cudaFuncSetAttribute(gemm_bf16_tc<4, false>,
        cudaFuncAttributeMaxDynamicSharedMemorySize, SMEM3_NT);

    // 0) zero accumulators; prep weights
    zero_aux<<<(BATCH * NPIX + 255) / 256, 256>>>(rowsum, ssum);
    prep_weights<<<(NQKV * CCH + CCH * CCH) / 256, 256>>>(
        wq, wk, wv, wo, bq, bk, bv, wqkv, wob, bqkv);

    // 1) GroupNorm -> hT bf16 [B][pix][C]  (4-way parallel stats)
    gn_stats_part<<<BATCH * 32 * 4, 256>>>(x, ssum);
    gn_apply_t_kernel<<<dim3(NPIX / 32, CCH / 32, BATCH), dim3(32, 8)>>>(
        x, gn_w, gn_b, ssum, ht);

    // 2) fused QKV: qkvT[pix][1536] = hT @ wqkv^T + bqkv[n]
    dim3 gQKV(NQKV / BN, NPIX / BM, BATCH);
    gemm_bf16_tc<1, false><<<gQKV, 256, SMEM3_NT>>>(
        ht, wqkv, qkv, bqkv, nullptr, CCH, CCH, CCH, NQKV,
        CN, 0, QKVN, 0, 0);

    // 3) P = exp(qT @ kT^T) -> bf16, rowsum accumulated
    dim3 gS(NPIX / BN, NPIX / BM, BATCH);
    gemm_bf16_tc<2, false><<<gS, 256, SMEM3_NT>>>(
        qkv, qkv + 512, p, rowsum, nullptr, CCH, NQKV, NQKV, NPIX,
        QKVN, QKVN, NN, NPIX, 0);

    // 4) OT[pix][C] = (P @ vT) / rowsum[pix]
    dim3 gAV(CCH / BN, NPIX / BM, BATCH);
    gemm_bf16_tc<3, true><<<gAV, 256, SMEM3_TR>>>(
        p, qkv + 1024, ot, rowsum, nullptr, NPIX, NPIX, NQKV, CCH,
        NN, QKVN, CN, NPIX, 0);

    // 5) out = x + wo @ OT^T + bo[m]  (fp32)
    dim3 gF(NPIX / BN, CCH / BM, BATCH);
    gemm_bf16_tc<4, false><<<gF, 256, SMEM3_NT>>>(
        wob, ot, out, bo, x, CCH, CCH, CCH, NPIX,
        0, CN, CN, 0, CN);
}

// round 11
// speedup vs baseline: 1.0701x; 1.0129x over previous
#include <cuda_runtime.h>
#include <cuda_bf16.h>
#include <cstdint>

// B=2, C=512, N=4096. out = x + Wo@Attn(GN(x)) + bo, [B,C,H,W] fp32.
#define BATCH 2
#define CCH   512
#define NPIX  4096
#define NQKV  1536
#define GEPS  1e-6f

static const long long CN   = (long long)CCH * NPIX;    // 2M
static const long long NN   = (long long)NPIX * NPIX;   // 16M
static const long long QKVN = (long long)NPIX * NQKV;   // 6M

// scratch (device globals)
__device__ __nv_bfloat16 g_ht [BATCH * NPIX * CCH];             // hT [B][pix][C]
__device__ __nv_bfloat16 g_qkv[(long long)BATCH * NPIX * NQKV]; // [B][pix][q|k|v]
__device__ __nv_bfloat16 g_p  [(long long)BATCH * NPIX * NPIX]; // exp(S) bf16
__device__ __nv_bfloat16 g_ot [BATCH * NPIX * CCH];             // OT [B][pix][C]
__device__ __nv_bfloat16 g_wqkv[NQKV * CCH];                    // concat(wq*s*lg2e,wk,wv)
__device__ __nv_bfloat16 g_wo [CCH * CCH];
__device__ float         g_bqkv[NQKV];
__device__ float         g_rowsum[BATCH * NPIX];                // softmax denominators
__device__ float         g_ssum4[BATCH * 32 * 4 * 2];           // GN partial (sum,sumsq)

// ---------------------------------------------------------------------------
// PTX helpers
// ---------------------------------------------------------------------------
__device__ __forceinline__ void cpasync16(uint32_t s, const void* g) {
    asm volatile("cp.async.cg.shared.global [%0], [%1], 16;" :: "r"(s), "l"(g));
}
__device__ __forceinline__ uint32_t smem_u32(const void* p) {
    return (uint32_t)__cvta_generic_to_shared(p);
}
__device__ __forceinline__ void ldsm4(uint32_t r[4], uint32_t addr) {
    asm volatile("ldmatrix.sync.aligned.m8n8.x4.shared.b16 {%0,%1,%2,%3}, [%4];"
        : "=r"(r[0]), "=r"(r[1]), "=r"(r[2]), "=r"(r[3]) : "r"(addr));
}
__device__ __forceinline__ void ldsm4t(uint32_t r[4], uint32_t addr) {
    asm volatile("ldmatrix.sync.aligned.m8n8.x4.trans.shared.b16 {%0,%1,%2,%3}, [%4];"
        : "=r"(r[0]), "=r"(r[1]), "=r"(r[2]), "=r"(r[3]) : "r"(addr));
}
__device__ __forceinline__ void mma_bf16(float c[4], const uint32_t a[4],
                                         const uint32_t b0, const uint32_t b1) {
    asm volatile(
        "mma.sync.aligned.m16n8k16.row.col.f32.bf16.bf16.f32 "
        "{%0,%1,%2,%3},{%4,%5,%6,%7},{%8,%9},{%0,%1,%2,%3};"
        : "+f"(c[0]), "+f"(c[1]), "+f"(c[2]), "+f"(c[3])
        : "r"(a[0]), "r"(a[1]), "r"(a[2]), "r"(a[3]), "r"(b0), "r"(b1));
}
__device__ __forceinline__ float ex2f(float x) {
    float y; asm("ex2.approx.ftz.f32 %0, %1;" : "=f"(y) : "f"(x));
    return y;
}

// ---------------------------------------------------------------------------
// bf16 tensor-core GEMM (R8/R10-best config): D[M][N] = A[M][K] * B^T
//   A bf16 [M][K]; TRB=0: B bf16 [N][K]; TRB=1: B bf16 [K][N] (ldmatrix.trans)
// Block 128x128x64, 256 thr = 8 warps (2x4), warp tile 64x32, m16n8k16,
// 3-stage cp.async, 2 CTAs/SM.
// EPI: 1 = bf16 out + bias[n]
//      2 = exp2 + bf16 out + rowsum atomics (aux=rowsum, stride sAux)
//      3 = bf16 out * (1/rowsum[m])
//      4 = fp32 out + bias[m] + residual
// ---------------------------------------------------------------------------
#define BM 128
#define BN 128
#define BK 64
#define ASTR 144
#define BSTR_N 144
#define BSTR_T 272
#define ASTAGE (BM * ASTR)
#define BSTAGE_N (BN * BSTR_N)
#define BSTAGE_T (BK * BSTR_T)
#define SMEM3_NT (3 * (ASTAGE + BSTAGE_N))   // 110592
#define SMEM3_TR (3 * (ASTAGE + BSTAGE_T))   // 107520

template<int EPI, bool TRB>
__global__ __launch_bounds__(256, 2) void gemm_bf16_tc(
    const __nv_bfloat16* __restrict__ A, const __nv_bfloat16* __restrict__ B,
    void* __restrict__ Cv,
    const float* __restrict__ aux, const float* __restrict__ res,
    int K, int lda, int ldb, int ldc,
    long long sA, long long sB, long long sC, long long sAux, long long sR)
{
    extern __shared__ char smem[];
    constexpr int BSTAGE = TRB ? BSTAGE_T : BSTAGE_N;
    const uint32_t sbA = smem_u32(smem);
    const uint32_t sbB = sbA + 3 * ASTAGE;

    const int tid  = threadIdx.x;
    const int wid  = tid >> 5;
    const int lane = tid & 31;
    const int g    = lane >> 2;
    const int tig  = lane & 3;
    const int sub  = lane >> 3;
    const int r8   = lane & 7;
    const int m_w  = (wid >> 2) * 64;
    const int n_w  = (wid & 3) * 32;
    const int m0   = blockIdx.y * BM;
    const int n0   = blockIdx.x * BN;
    const int z    = blockIdx.z;

    const __nv_bfloat16* Ab = A + (long long)z * sA + (long long)m0 * lda;
    const __nv_bfloat16* Bb = TRB ? (B + (long long)z * sB + n0)
                                  : (B + (long long)z * sB + (long long)n0 * ldb);

    float acc[4][4][4];
    #pragma unroll
    for (int i = 0; i < 4; i++)
        #pragma unroll
        for (int j = 0; j < 4; j++)
            #pragma unroll
            for (int r = 0; r < 4; r++) acc[i][j][r] = 0.f;

    const int nk = K / BK;

    auto load = [&](int ks, int buf) {
        const uint32_t ab = sbA + buf * ASTAGE;
        const uint32_t bb = sbB + buf * BSTAGE;
        #pragma unroll
        for (int it = 0; it < 4; it++) {
            int s = tid + it * 256;
            int r = s >> 3, c = s & 7;
            cpasync16(ab + r * ASTR + c * 16,
                      Ab + (long long)r * lda + ks * BK + c * 8);
        }
        if (!TRB) {
            #pragma unroll
            for (int it = 0; it < 4; it++) {
                int s = tid + it * 256;
                int r = s >> 3, c = s & 7;
                cpasync16(bb + r * BSTR_N + c * 16,
                          Bb + (long long)r * ldb + ks * BK + c * 8);
            }
        } else {
            #pragma unroll
            for (int it = 0; it < 4; it++) {
                int s = tid + it * 256;
                int r = s >> 4, c = s & 15;
                cpasync16(bb + r * BSTR_T + c * 16,
                          Bb + (long long)(ks * BK + r) * ldb + c * 8);
            }
        }
        asm volatile("cp.async.commit_group;");
    };

    load(0, 0);
    if (nk > 1) load(1, 1);

    #pragma unroll 1
    for (int ks = 0; ks < nk; ks++) {
        const int buf = ks % 3;
        if (ks + 1 < nk) asm volatile("cp.async.wait_group 1;");
        else             asm volatile("cp.async.wait_group 0;");
        __syncthreads();
        if (ks + 2 < nk) load(ks + 2, (ks + 2) % 3);

        const uint32_t ab = sbA + buf * ASTAGE;
        const uint32_t bb = sbB + buf * BSTAGE;

        #pragma unroll
        for (int kk = 0; kk < 4; kk++) {
            uint32_t af[4][4];
            #pragma unroll
            for (int i = 0; i < 4; i++) {
                uint32_t addr = ab + (m_w + 16 * i + (sub & 1) * 8 + r8) * ASTR
                              + kk * 32 + (sub >> 1) * 16;
                ldsm4(af[i], addr);
            }
            uint32_t bf[4][2];
            #pragma unroll
            for (int jj = 0; jj < 2; jj++) {
                uint32_t t[4];
                if (!TRB) {
                    uint32_t addr = bb + (n_w + 16 * jj + (sub >> 1) * 8 + r8) * BSTR_N
                                  + kk * 32 + (sub & 1) * 16;
                    ldsm4(t, addr);
                } else {
                    uint32_t addr = bb + (kk * 16 + (sub & 1) * 8 + r8) * BSTR_T
                                  + (n_w + 16 * jj + (sub >> 1) * 8) * 2;
                    ldsm4t(t, addr);
                }
                bf[2 * jj][0] = t[0]; bf[2 * jj][1] = t[1];
                bf[2 * jj + 1][0] = t[2]; bf[2 * jj + 1][1] = t[3];
            }
            #pragma unroll
            for (int i = 0; i < 4; i++)
                #pragma unroll
                for (int j = 0; j < 4; j++)
                    mma_bf16(acc[i][j], af[i], bf[j][0], bf[j][1]);
        }
    }

    // ------------------------------ epilogues ------------------------------
    if (EPI == 1) {           // bf16 out + bias[n]
        __nv_bfloat16* C = (__nv_bfloat16*)Cv + (long long)z * sC;
        #pragma unroll
        for (int i = 0; i < 4; i++) {
            int r0 = m0 + m_w + 16 * i + g, r1 = r0 + 8;
            #pragma unroll
            for (int j = 0; j < 4; j++) {
                int col = n0 + n_w + 8 * j + 2 * tig;
                float bn0 = aux[col], bn1 = aux[col + 1];
                *(__nv_bfloat162*)&C[(long long)r0 * ldc + col] =
                    __float22bfloat162_rn(make_float2(acc[i][j][0] + bn0,
                                                      acc[i][j][1] + bn1));
                *(__nv_bfloat162*)&C[(long long)r1 * ldc + col] =
                    __float22bfloat162_rn(make_float2(acc[i][j][2] + bn0,
                                                      acc[i][j][3] + bn1));
            }
        }
    } else if (EPI == 2) {    // exp2, bf16 out, rowsum atomics
        __nv_bfloat16* C = (__nv_bfloat16*)Cv + (long long)z * sC;
        float* rs = (float*)aux + (long long)z * sAux;
        #pragma unroll
        for (int i = 0; i < 4; i++) {
            int r0 = m0 + m_w + 16 * i + g, r1 = r0 + 8;
            float s0 = 0.f, s1 = 0.f;
            #pragma unroll
            for (int j = 0; j < 4; j++) {
                int col = n0 + n_w + 8 * j + 2 * tig;
                float e0 = ex2f(acc[i][j][0]);
                float e1 = ex2f(acc[i][j][1]);
                float e2 = ex2f(acc[i][j][2]);
                float e3 = ex2f(acc[i][j][3]);
                s0 += e0 + e1; s1 += e2 + e3;
                *(__nv_bfloat162*)&C[(long long)r0 * ldc + col] =
                    __float22bfloat162_rn(make_float2(e0, e1));
                *(__nv_bfloat162*)&C[(long long)r1 * ldc + col] =
                    __float22bfloat162_rn(make_float2(e2, e3));
            }
            s0 += __shfl_xor_sync(0xffffffffu, s0, 1);
            s0 += __shfl_xor_sync(0xffffffffu, s0, 2);
            s1 += __shfl_xor_sync(0xffffffffu, s1, 1);
            s1 += __shfl_xor_sync(0xffffffffu, s1, 2);
            if (tig == 0) {
                atomicAdd(&rs[r0], s0);
                atomicAdd(&rs[r1], s1);
            }
        }
    } else if (EPI == 3) {    // bf16 out scaled by 1/rowsum[m]
        __nv_bfloat16* C = (__nv_bfloat16*)Cv + (long long)z * sC;
        const float* rs = aux + (long long)z * sAux;
        #pragma unroll
        for (int i = 0; i < 4; i++) {
            int r0 = m0 + m_w + 16 * i + g, r1 = r0 + 8;
            float i0 = 1.f / rs[r0];
            float i1 = 1.f / rs[r1];
            #pragma unroll
            for (int j = 0; j < 4; j++) {
                int col = n0 + n_w + 8 * j + 2 * tig;
                *(__nv_bfloat162*)&C[(long long)r0 * ldc + col] =
                    __float22bfloat162_rn(make_float2(acc[i][j][0] * i0,
                                                      acc[i][j][1] * i0));
                *(__nv_bfloat162*)&C[(long long)r1 * ldc + col] =
                    __float22bfloat162_rn(make_float2(acc[i][j][2] * i1,
                                                      acc[i][j][3] * i1));
            }
        }
    } else {                  // EPI == 4: fp32 out + bias[m] + residual
        float* C = (float*)Cv + (long long)z * sC;
        const float* Rb = res + (long long)z * sR;
        #pragma unroll
        for (int i = 0; i < 4; i++) {
            int r0 = m0 + m_w + 16 * i + g, r1 = r0 + 8;
            float bm0 = aux[r0], bm1 = aux[r1];
            #pragma unroll
            for (int j = 0; j < 4; j++) {
                int col = n0 + n_w + 8 * j + 2 * tig;
                long long o0 = (long long)r0 * ldc + col;
                long long o1 = (long long)r1 * ldc + col;
                float2 a0 = *(const float2*)&Rb[o0];
                float2 a1 = *(const float2*)&Rb[o1];
                float2 v0 = make_float2(acc[i][j][0] + bm0 + a0.x,
                                        acc[i][j][1] + bm0 + a0.y);
                float2 v1 = make_float2(acc[i][j][2] + bm1 + a1.x,
                                        acc[i][j][3] + bm1 + a1.y);
                *(float2*)&C[o0] = v0;
                *(float2*)&C[o1] = v1;
            }
        }
    }
}

// ---------------------------------------------------------------------------
// Fused prologue: [0,4096) weight prep | [4096,4352) GN partial stats |
// [4352,4384) rowsum zero. One launch, no cross-range dependencies.
// ---------------------------------------------------------------------------
#define PREP_BLOCKS 4096      // (NQKV*CCH + CCH*CCH) / 256
#define STAT_BLOCKS 256       // BATCH*32 groups x 4 parts
#define ZERO_BLOCKS 32        // BATCH*NPIX / 256

__global__ __launch_bounds__(256) void prologue_kernel(
    const float* __restrict__ x,
    const float* __restrict__ wq, const float* __restrict__ wk,
    const float* __restrict__ wv, const float* __restrict__ wo,
    const float* __restrict__ bq, const float* __restrict__ bk,
    const float* __restrict__ bv,
    __nv_bfloat16* __restrict__ wqkv, __nv_bfloat16* __restrict__ wob,
    float* __restrict__ bqkv, float* __restrict__ ssum4,
    float* __restrict__ rowsum)
{
    const int blk = blockIdx.x;
    const int t = threadIdx.x;

    if (blk < PREP_BLOCKS) {
        // scale = C^-0.5 * log2(e) folded into wq/bq so S epilogue uses ex2
        const float qscale = 0.044194173824159216f * 1.4426950408889634f;
        int idx = blk * 256 + t;
        if (idx < NQKV * CCH) {
            int row = idx >> 9, col = idx & 511;
            int which = row >> 9, rr = row & 511;
            float v = which == 0 ? wq[rr * 512 + col] * qscale
                    : which == 1 ? wk[rr * 512 + col]
                                 : wv[rr * 512 + col];
            wqkv[idx] = __float2bfloat16_rn(v);
            if (idx < NQKV) {
                int w2 = idx >> 9, r2 = idx & 511;
                bqkv[idx] = w2 == 0 ? bq[r2] * qscale
                          : w2 == 1 ? bk[r2] : bv[r2];
            }
        } else {
            int j = idx - NQKV * CCH;
            wob[j] = __float2bfloat16_rn(wo[j]);
        }
    } else if (blk < PREP_BLOCKS + STAT_BLOCKS) {
        // GN partial stats: pb in [0,256): bg = pb>>2, part = pb&3
        const int pb = blk - PREP_BLOCKS;
        const long long base = (long long)(pb >> 2) * 65536 + (pb & 3) * 16384;
        float s = 0.f, ss = 0.f;
        #pragma unroll 4
        for (int i = t; i < 16384; i += 256) {
            float v = x[base + i];
            s += v; ss += v * v;
        }
        #pragma unroll
        for (int off = 16; off; off >>= 1) {
            s  += __shfl_down_sync(0xffffffffu, s,  off);
            ss += __shfl_down_sync(0xffffffffu, ss, off);
        }
        __shared__ float shs[8], shss[8];
        int wid = t >> 5, lane = t & 31;
        if (lane == 0) { shs[wid] = s; shss[wid] = ss; }
        __syncthreads();
        if (t == 0) {
            float ts = 0.f, tss = 0.f;
            #pragma unroll
            for (int i = 0; i < 8; i++) { ts += shs[i]; tss += shss[i]; }
            ssum4[2 * pb]     = ts;
            ssum4[2 * pb + 1] = tss;
        }
    } else {
        int idx = (blk - PREP_BLOCKS - STAT_BLOCKS) * 256 + t;
        rowsum[idx] = 0.f;
    }
}

// ---------------------------------------------------------------------------
// GN apply + transpose (bf16 out); sums 4 stat partials inline
// ---------------------------------------------------------------------------
__global__ __launch_bounds__(256) void gn_apply_t_kernel(
    const float* __restrict__ x, const float* __restrict__ w,
    const float* __restrict__ b, const float* __restrict__ ssum4,
    __nv_bfloat16* __restrict__ ht)
{
    __shared__ float tile[32][33];
    const int p0 = blockIdx.x * 32;
    const int c0 = blockIdx.y * 32;
    const int bb = blockIdx.z;
    const int tx = threadIdx.x, ty = threadIdx.y;   // (32, 8)
    const long long xb = (long long)bb * CN;

    #pragma unroll
    for (int r = 0; r < 4; r++) {
        int cl = ty + 8 * r;
        tile[cl][tx] = x[xb + (long long)(c0 + cl) * NPIX + p0 + tx];
    }
    __syncthreads();
    const int c = c0 + tx;
    const int gidx = c >> 4;
    const int bg = bb * 32 + gidx;
    float ts = 0.f, tss = 0.f;
    #pragma unroll
    for (int pp = 0; pp < 4; pp++) {
        ts  += ssum4[2 * (bg * 4 + pp)];
        tss += ssum4[2 * (bg * 4 + pp) + 1];
    }
    const float mean = ts * (1.f / 65536.f);
    const float var  = tss * (1.f / 65536.f) - mean * mean;
    const float rstd = rsqrtf(var + GEPS);
    const float sc = rstd * w[c];
    const float sh = b[c] - mean * sc;
    #pragma unroll
    for (int r = 0; r < 4; r++) {
        int pl = ty + 8 * r;
        float v = tile[tx][pl] * sc + sh;
        ht[xb + (long long)(p0 + pl) * CCH + c] = __float2bfloat16_rn(v);
    }
}

// ---------------------------------------------------------------------------
extern "C" void kernel_launch(void* const* d_in, const int* in_sizes, int n_in,
                              void* d_out, int out_size)
{
    const float* x    = (const float*)d_in[0];
    const float* gn_w = (const float*)d_in[1];
    const float* gn_b = (const float*)d_in[2];
    const float* wq   = (const float*)d_in[3];
    const float* bq   = (const float*)d_in[4];
    const float* wk   = (const float*)d_in[5];
    const float* bk   = (const float*)d_in[6];
    const float* wv   = (const float*)d_in[7];
    const float* bv   = (const float*)d_in[8];
    const float* wo   = (const float*)d_in[9];
    const float* bo   = (const float*)d_in[10];
    float* out = (float*)d_out;

    __nv_bfloat16 *ht, *qkv, *p, *ot, *wqkv, *wob;
    float *bqkv, *ssum4, *rowsum;
    cudaGetSymbolAddress((void**)&ht,     g_ht);
    cudaGetSymbolAddress((void**)&qkv,    g_qkv);
    cudaGetSymbolAddress((void**)&p,      g_p);
    cudaGetSymbolAddress((void**)&ot,     g_ot);
    cudaGetSymbolAddress((void**)&wqkv,   g_wqkv);
    cudaGetSymbolAddress((void**)&wob,    g_wo);
    cudaGetSymbolAddress((void**)&bqkv,   g_bqkv);
    cudaGetSymbolAddress((void**)&ssum4,  g_ssum4);
    cudaGetSymbolAddress((void**)&rowsum, g_rowsum);

    cudaFuncSetAttribute(gemm_bf16_tc<1, false>,
        cudaFuncAttributeMaxDynamicSharedMemorySize, SMEM3_NT);
    cudaFuncSetAttribute(gemm_bf16_tc<2, false>,
        cudaFuncAttributeMaxDynamicSharedMemorySize, SMEM3_NT);
    cudaFuncSetAttribute(gemm_bf16_tc<3, true>,
        cudaFuncAttributeMaxDynamicSharedMemorySize, SMEM3_TR);
    cudaFuncSetAttribute(gemm_bf16_tc<4, false>,
        cudaFuncAttributeMaxDynamicSharedMemorySize, SMEM3_NT);

    // 0) fused prologue: weight prep + GN partial stats + rowsum zero
    prologue_kernel<<<PREP_BLOCKS + STAT_BLOCKS + ZERO_BLOCKS, 256>>>(
        x, wq, wk, wv, wo, bq, bk, bv, wqkv, wob, bqkv, ssum4, rowsum);

    // 1) GN apply + transpose -> hT bf16 [B][pix][C]
    gn_apply_t_kernel<<<dim3(NPIX / 32, CCH / 32, BATCH), dim3(32, 8)>>>(
        x, gn_w, gn_b, ssum4, ht);

    // 2) fused QKV: qkvT[pix][1536] = hT @ wqkv^T + bqkv[n]
    dim3 gQKV(NQKV / BN, NPIX / BM, BATCH);
    gemm_bf16_tc<1, false><<<gQKV, 256, SMEM3_NT>>>(
        ht, wqkv, qkv, bqkv, nullptr, CCH, CCH, CCH, NQKV,
        CN, 0, QKVN, 0, 0);

    // 3) P = exp2(qT @ kT^T) -> bf16, rowsum accumulated (log2e pre-folded)
    dim3 gS(NPIX / BN, NPIX / BM, BATCH);
    gemm_bf16_tc<2, false><<<gS, 256, SMEM3_NT>>>(
        qkv, qkv + 512, p, rowsum, nullptr, CCH, NQKV, NQKV, NPIX,
        QKVN, QKVN, NN, NPIX, 0);

    // 4) OT[pix][C] = (P @ vT) / rowsum[pix]
    dim3 gAV(CCH / BN, NPIX / BM, BATCH);
    gemm_bf16_tc<3, true><<<gAV, 256, SMEM3_TR>>>(
        p, qkv + 1024, ot, rowsum, nullptr, NPIX, NPIX, NQKV, CCH,
        NN, QKVN, CN, NPIX, 0);

    // 5) out = x + wo @ OT^T + bo[m]  (fp32)
    dim3 gF(NPIX / BN, CCH / BM, BATCH);
    gemm_bf16_tc<4, false><<<gF, 256, SMEM3_NT>>>(
        wob, ot, out, bo, x, CCH, CCH, CCH, NPIX,
        0, CN, CN, 0, CN);
}